// round 15
// baseline (speedup 1.0000x reference)
#include <cuda_runtime.h>
#include <cstdint>
#include <cstddef>

#define NN    10000
#define KNBR  16
#define LDGG  10016
#define NBLD  1792
#define EE    (NN*KNBR)

#define NBLK  79
#define SPAD  136
typedef unsigned long long u64;

// Fragment-major global arrays (layouts documented in R10).
static __device__ float g_xAh[(size_t)NBLK * 32768];
static __device__ float g_xAl[(size_t)NBLK * 32768];
static __device__ float g_xBh[(size_t)NBLK * 32768];
static __device__ float g_xBl[(size_t)NBLK * 32768];
static __device__ float g_WBh[(size_t)14 * 32768];
static __device__ float g_WBl[(size_t)14 * 32768];

static __device__ float g_G[(size_t)NN * LDGG];
static __device__ float g_NB[(size_t)NN * NBLD];     // 0:Qa 1:Qb(+bq) 2:Ka 3:Kb(+bk) 4:P(+b1) 5:R 6:S(+b2)
static __device__ float g_bias[NBLD];
static __device__ float g_n2[NN];
static __device__ int   g_nbr[EE];
static __device__ float g_U[(size_t)EE * 256];

// ---------------------------------------------------------------------------
// helpers
// ---------------------------------------------------------------------------
__device__ __forceinline__ uint32_t f2tf(float v) {
    uint32_t u; asm("cvt.rna.tf32.f32 %0, %1;" : "=r"(u) : "f"(v)); return u;
}
__device__ __forceinline__ float2 split_tf(float v) {
    uint32_t hi = f2tf(v);
    uint32_t lo = f2tf(v - __uint_as_float(hi));
    return make_float2(__uint_as_float(hi), __uint_as_float(lo));
}
__device__ __forceinline__ void mma8(float c[4], const uint32_t a[4], uint32_t b0, uint32_t b1) {
    asm volatile(
        "mma.sync.aligned.m16n8k8.row.col.f32.tf32.tf32.f32 "
        "{%0,%1,%2,%3}, {%4,%5,%6,%7}, {%8,%9}, {%0,%1,%2,%3};"
        : "+f"(c[0]), "+f"(c[1]), "+f"(c[2]), "+f"(c[3])
        : "r"(a[0]), "r"(a[1]), "r"(a[2]), "r"(a[3]), "r"(b0), "r"(b1));
}
#define FU(x) __float_as_uint(x)

__device__ __forceinline__ void cpa16(uint32_t dst, const void* src) {
    asm volatile("cp.async.cg.shared.global [%0], [%1], 16;" :: "r"(dst), "l"(src));
}
#define CP_COMMIT() asm volatile("cp.async.commit_group;" ::: "memory")
#define CP_WAIT0()  asm volatile("cp.async.wait_group 0;" ::: "memory")

// K=16 stage, both operands fragment-major (2048 floats per array per stage).
__device__ __forceinline__ void mma_stage_ff(
    const float* sAh, const float* sAl, const float* sBh, const float* sBl,
    int a4base, int b2base, int wm, int wn, int lane, float c[4][4][4]) {
    #pragma unroll
    for (int kc = 0; kc < 2; kc++) {
        float2 bh[4], bl[4];
        #pragma unroll
        for (int nf = 0; nf < 4; nf++) {
            int bi = b2base + (kc * 16 + wn * 4 + nf) * 32 + lane;
            bh[nf] = ((const float2*)sBh)[bi];
            bl[nf] = ((const float2*)sBl)[bi];
        }
        #pragma unroll
        for (int mf = 0; mf < 4; mf++) {
            int ai = a4base + (kc * 8 + wm * 4 + mf) * 32 + lane;
            float4 vh = ((const float4*)sAh)[ai];
            float4 vl = ((const float4*)sAl)[ai];
            uint32_t ah[4] = {FU(vh.x), FU(vh.y), FU(vh.z), FU(vh.w)};
            uint32_t al[4] = {FU(vl.x), FU(vl.y), FU(vl.z), FU(vl.w)};
            #pragma unroll
            for (int nf = 0; nf < 4; nf++) {
                mma8(c[mf][nf], ah, FU(bh[nf].x), FU(bh[nf].y));
                mma8(c[mf][nf], al, FU(bh[nf].x), FU(bh[nf].y));
                mma8(c[mf][nf], ah, FU(bl[nf].x), FU(bl[nf].y));
            }
        }
    }
}

// K=32 chunk, A classic [k][m+SPAD], B fragment-major (edge kernel).
__device__ __forceinline__ void mma_chunk_cf(
    const float (*Ah)[SPAD], const float (*Al)[SPAD],
    const float* sBh, const float* sBl,
    int wm, int wn, int lane, float c[4][4][4]) {
    int r = lane >> 2, cl = lane & 3;
    #pragma unroll
    for (int kc = 0; kc < 4; kc++) {
        float2 bh[4], bl[4];
        #pragma unroll
        for (int nf = 0; nf < 4; nf++) {
            int bi = (kc * 16 + wn * 4 + nf) * 32 + lane;
            bh[nf] = ((const float2*)sBh)[bi];
            bl[nf] = ((const float2*)sBl)[bi];
        }
        int k0 = kc * 8;
        #pragma unroll
        for (int mf = 0; mf < 4; mf++) {
            int rb = wm * 64 + mf * 16 + r;
            uint32_t ah[4] = {FU(Ah[k0 + cl][rb]),     FU(Ah[k0 + cl][rb + 8]),
                              FU(Ah[k0 + cl + 4][rb]), FU(Ah[k0 + cl + 4][rb + 8])};
            uint32_t al[4] = {FU(Al[k0 + cl][rb]),     FU(Al[k0 + cl][rb + 8]),
                              FU(Al[k0 + cl + 4][rb]), FU(Al[k0 + cl + 4][rb + 8])};
            #pragma unroll
            for (int nf = 0; nf < 4; nf++) {
                mma8(c[mf][nf], ah, FU(bh[nf].x), FU(bh[nf].y));
                mma8(c[mf][nf], al, FU(bh[nf].x), FU(bh[nf].y));
                mma8(c[mf][nf], ah, FU(bl[nf].x), FU(bl[nf].y));
            }
        }
    }
}

// ---------------------------------------------------------------------------
// Pre-transform x -> fragment-major A and B layouts (hi/lo).  grid (8, 79).
// ---------------------------------------------------------------------------
__global__ void xfrag_kernel(const float* __restrict__ x) {
    __shared__ float sh[32][129];
    __shared__ float sl[32][129];
    int blk = blockIdx.y, chunk = blockIdx.x, t = threadIdx.x;

    #pragma unroll
    for (int i = 0; i < 4; i++) {
        int idx = t + i * 256;
        int m  = idx >> 3;
        int kq = (idx & 7) * 4;
        int row = blk * 128 + m; if (row >= NN) row = NN - 1;
        float4 v = *(const float4*)(x + (size_t)row * 256 + chunk * 32 + kq);
        float2 s0 = split_tf(v.x), s1 = split_tf(v.y), s2 = split_tf(v.z), s3 = split_tf(v.w);
        sh[kq + 0][m] = s0.x; sh[kq + 1][m] = s1.x; sh[kq + 2][m] = s2.x; sh[kq + 3][m] = s3.x;
        sl[kq + 0][m] = s0.y; sl[kq + 1][m] = s1.y; sl[kq + 2][m] = s2.y; sl[kq + 3][m] = s3.y;
    }
    __syncthreads();

    size_t base = ((size_t)blk * 8 + chunk) * 4096;
    #pragma unroll
    for (int i = 0; i < 16; i++) {
        int o = t + i * 256;
        int reg = o & 3, lane = (o >> 2) & 31, wmmf = (o >> 7) & 7, kc = o >> 10;
        int r = lane >> 2, cl = lane & 3, half = reg >> 1, sel = reg & 1;
        int k = kc * 8 + half * 4 + cl;
        int m = wmmf * 16 + sel * 8 + r;
        g_xAh[base + o] = sh[k][m];
        g_xAl[base + o] = sl[k][m];
        int regb = o & 1, laneb = (o >> 1) & 31, wnnf = (o >> 6) & 15, kcb = o >> 10;
        int rb2 = laneb >> 2, clb = laneb & 3;
        int kb = kcb * 8 + regb * 4 + clb;
        int nb = wnnf * 8 + rb2;
        g_xBh[base + o] = sh[kb][nb];
        g_xBl[base + o] = sl[kb][nb];
    }
}

// ---------------------------------------------------------------------------
// Pre-transform Wcat^T -> fragment-major B layout.  grid (8, 14).
// ---------------------------------------------------------------------------
__global__ void wfrag_kernel(const float* __restrict__ Wq,
                             const float* __restrict__ Wk,
                             const float* __restrict__ W1,
                             const float* __restrict__ W2) {
    __shared__ float sh[32][129];
    __shared__ float sl[32][129];
    int nblk = blockIdx.y, chunk = blockIdx.x, t = threadIdx.x;
    int b = nblk >> 1;
    int cbase = (nblk & 1) * 128;

    #pragma unroll
    for (int i = 0; i < 4; i++) {
        int idx = t + i * 256;
        int kk = idx >> 5;
        int n4 = (idx & 31) * 4;
        int k = chunk * 32 + kk;
        int c = cbase + n4;
        const float* src;
        switch (b) {
            case 0: src = Wq + (size_t)k * 256 + c;         break;
            case 1: src = Wq + (size_t)(k + 256) * 256 + c; break;
            case 2: src = Wk + (size_t)k * 256 + c;         break;
            case 3: src = Wk + (size_t)(k + 256) * 256 + c; break;
            case 4: src = W1 + (size_t)k * 256 + c;         break;
            case 5: src = W1 + (size_t)(k + 256) * 256 + c; break;
            default: src = W2 + (size_t)k * 256 + c;        break;
        }
        float4 v = *(const float4*)src;
        float2 s0 = split_tf(v.x), s1 = split_tf(v.y), s2 = split_tf(v.z), s3 = split_tf(v.w);
        sh[kk][n4 + 0] = s0.x; sh[kk][n4 + 1] = s1.x; sh[kk][n4 + 2] = s2.x; sh[kk][n4 + 3] = s3.x;
        sl[kk][n4 + 0] = s0.y; sl[kk][n4 + 1] = s1.y; sl[kk][n4 + 2] = s2.y; sl[kk][n4 + 3] = s3.y;
    }
    __syncthreads();

    size_t base = ((size_t)nblk * 8 + chunk) * 4096;
    #pragma unroll
    for (int i = 0; i < 16; i++) {
        int o = t + i * 256;
        int reg = o & 1, lane = (o >> 1) & 31, wnnf = (o >> 6) & 15, kc = o >> 10;
        int r = lane >> 2, cl = lane & 3;
        int k = kc * 8 + reg * 4 + cl;
        int n = wnnf * 8 + r;
        g_WBh[base + o] = sh[k][n];
        g_WBl[base + o] = sl[k][n];
    }
}

__global__ void build_bias_kernel(const float* __restrict__ bq,
                                  const float* __restrict__ bk,
                                  const float* __restrict__ b1,
                                  const float* __restrict__ b2) {
    int n = blockIdx.x * 256 + threadIdx.x;
    int b = n >> 8, c = n & 255;
    float v = 0.f;
    if (b == 1) v = bq[c];
    else if (b == 3) v = bk[c];
    else if (b == 4) v = b1[c];
    else if (b == 6) v = b2[c];
    g_bias[n] = v;
}

__global__ void norms_kernel(const float* __restrict__ x) {
    int row  = blockIdx.x * 8 + (threadIdx.x >> 5);
    int lane = threadIdx.x & 31;
    const float4* xr = (const float4*)(x + (size_t)row * 256);
    float s = 0.f;
    #pragma unroll
    for (int r = 0; r < 2; r++) {
        float4 v = xr[lane + 32 * r];
        s += v.x * v.x + v.y * v.y + v.z * v.z + v.w * v.w;
    }
    #pragma unroll
    for (int o = 16; o; o >>= 1) s += __shfl_xor_sync(0xffffffffu, s, o);
    if (lane == 0) g_n2[row] = s;
}

// ---------------------------------------------------------------------------
// Pipelined staging
// ---------------------------------------------------------------------------
__device__ __forceinline__ void stage_issue(
    uint32_t uAh, uint32_t uAl, uint32_t uBh, uint32_t uBl,
    const float* gAh, const float* gAl, const float* gBh, const float* gBl,
    size_t aB, size_t bB, int buf, int t) {
    #pragma unroll
    for (int i = 0; i < 2; i++) {
        int f = t + i * 256;
        uint32_t doff = (uint32_t)(buf * 512 + f) * 16;
        cpa16(uAh + doff, gAh + aB + 4 * f);
        cpa16(uAl + doff, gAl + aB + 4 * f);
        cpa16(uBh + doff, gBh + bB + 4 * f);
        cpa16(uBl + doff, gBl + bB + 4 * f);
    }
    CP_COMMIT();
}

// ---------------------------------------------------------------------------
// Node GEMM: g_NB = x @ Wcat + bias.  grid (14, 79), 256 thr, smem 64 KB.
// ---------------------------------------------------------------------------
__global__ void __launch_bounds__(256, 2) node_mma_kernel() {
    extern __shared__ float smem_f[];
    float* sAh = smem_f;
    float* sAl = smem_f + 4096;
    float* sBh = smem_f + 8192;
    float* sBl = smem_f + 12288;
    uint32_t uAh = (uint32_t)__cvta_generic_to_shared(sAh);
    uint32_t uAl = (uint32_t)__cvta_generic_to_shared(sAl);
    uint32_t uBh = (uint32_t)__cvta_generic_to_shared(sBh);
    uint32_t uBl = (uint32_t)__cvta_generic_to_shared(sBl);

    int t = threadIdx.x, lane = t & 31, wid = t >> 5;
    int wm = wid >> 2, wn = wid & 3;
    int m0 = blockIdx.y * 128, n0 = blockIdx.x * 128;
    size_t aBase = (size_t)blockIdx.y * 32768;
    size_t bBase = (size_t)blockIdx.x * 32768;

    float c[4][4][4];
    #pragma unroll
    for (int a = 0; a < 4; a++)
        #pragma unroll
        for (int b = 0; b < 4; b++)
            #pragma unroll
            for (int d = 0; d < 4; d++) c[a][b][d] = 0.f;

    stage_issue(uAh, uAl, uBh, uBl, g_xAh, g_xAl, g_WBh, g_WBl, aBase, bBase, 0, t);
    for (int cs = 0; cs < 16; cs++) {
        int buf = cs & 1;
        CP_WAIT0();
        __syncthreads();
        if (cs < 15)
            stage_issue(uAh, uAl, uBh, uBl, g_xAh, g_xAl, g_WBh, g_WBl,
                        aBase + (cs + 1) * 2048, bBase + (cs + 1) * 2048, buf ^ 1, t);
        mma_stage_ff(sAh, sAl, sBh, sBl, buf * 512, buf * 1024, wm, wn, lane, c);
        __syncthreads();
    }

    int r = lane >> 2, q = lane & 3;
    #pragma unroll
    for (int mf = 0; mf < 4; mf++) {
        #pragma unroll
        for (int nf = 0; nf < 4; nf++) {
            int row = m0 + wm * 64 + mf * 16 + r;
            int col = n0 + wn * 32 + nf * 8 + 2 * q;
            float b0 = g_bias[col], b1 = g_bias[col + 1];
            if (row < NN)
                *(float2*)(g_NB + (size_t)row * NBLD + col) =
                    make_float2(c[mf][nf][0] + b0, c[mf][nf][1] + b1);
            if (row + 8 < NN)
                *(float2*)(g_NB + (size_t)(row + 8) * NBLD + col) =
                    make_float2(c[mf][nf][2] + b0, c[mf][nf][3] + b1);
        }
    }
}

// ---------------------------------------------------------------------------
// Gram: G = x @ x^T, upper tiles + mirror.  grid (79, 79), 256 thr.
// ---------------------------------------------------------------------------
__global__ void __launch_bounds__(256, 2) gram_mma_kernel() {
    if (blockIdx.x < blockIdx.y) return;
    extern __shared__ float smem_f[];
    float* sAh = smem_f;
    float* sAl = smem_f + 4096;
    float* sBh = smem_f + 8192;
    float* sBl = smem_f + 12288;
    uint32_t uAh = (uint32_t)__cvta_generic_to_shared(sAh);
    uint32_t uAl = (uint32_t)__cvta_generic_to_shared(sAl);
    uint32_t uBh = (uint32_t)__cvta_generic_to_shared(sBh);
    uint32_t uBl = (uint32_t)__cvta_generic_to_shared(sBl);

    int t = threadIdx.x, lane = t & 31, wid = t >> 5;
    int wm = wid >> 2, wn = wid & 3;
    int m0 = blockIdx.y * 128, n0 = blockIdx.x * 128;
    bool diag = (blockIdx.x == blockIdx.y);
    size_t aBase = (size_t)blockIdx.y * 32768;
    size_t bBase = (size_t)blockIdx.x * 32768;

    float c[4][4][4];
    #pragma unroll
    for (int a = 0; a < 4; a++)
        #pragma unroll
        for (int b = 0; b < 4; b++)
            #pragma unroll
            for (int d = 0; d < 4; d++) c[a][b][d] = 0.f;

    stage_issue(uAh, uAl, uBh, uBl, g_xAh, g_xAl, g_xBh, g_xBl, aBase, bBase, 0, t);
    for (int cs = 0; cs < 16; cs++) {
        int buf = cs & 1;
        CP_WAIT0();
        __syncthreads();
        if (cs < 15)
            stage_issue(uAh, uAl, uBh, uBl, g_xAh, g_xAl, g_xBh, g_xBl,
                        aBase + (cs + 1) * 2048, bBase + (cs + 1) * 2048, buf ^ 1, t);
        mma_stage_ff(sAh, sAl, sBh, sBl, buf * 512, buf * 1024, wm, wn, lane, c);
        __syncthreads();
    }

    int r = lane >> 2, q = lane & 3;
    // direct store (upper tile)
    #pragma unroll
    for (int mf = 0; mf < 4; mf++) {
        #pragma unroll
        for (int nf = 0; nf < 4; nf++) {
            int row = m0 + wm * 64 + mf * 16 + r;
            int col = n0 + wn * 32 + nf * 8 + 2 * q;
            if (col + 1 < NN) {
                if (row < NN)
                    *(float2*)(g_G + (size_t)row * LDGG + col) =
                        make_float2(c[mf][nf][0], c[mf][nf][1]);
                if (row + 8 < NN)
                    *(float2*)(g_G + (size_t)(row + 8) * LDGG + col) =
                        make_float2(c[mf][nf][2], c[mf][nf][3]);
            } else if (col < NN) {
                if (row < NN)     g_G[(size_t)row * LDGG + col]       = c[mf][nf][0];
                if (row + 8 < NN) g_G[(size_t)(row + 8) * LDGG + col] = c[mf][nf][2];
            }
        }
    }

    // mirror store (off-diag)
    if (!diag) {
        float* sT = smem_f;
        for (int h = 0; h < 2; h++) {
            __syncthreads();
            if ((wn >> 1) == h) {
                #pragma unroll
                for (int mf = 0; mf < 4; mf++) {
                    #pragma unroll
                    for (int nf = 0; nf < 4; nf++) {
                        int rowl = wm * 64 + mf * 16 + r;
                        int cn   = (wn & 1) * 32 + nf * 8 + 2 * q;
                        sT[cn * 132 + rowl]           = c[mf][nf][0];
                        sT[(cn + 1) * 132 + rowl]     = c[mf][nf][1];
                        sT[cn * 132 + rowl + 8]       = c[mf][nf][2];
                        sT[(cn + 1) * 132 + rowl + 8] = c[mf][nf][3];
                    }
                }
            }
            __syncthreads();
            int n    = t >> 2;
            int part = t & 3;
            int gn = n0 + h * 64 + n;
            if (gn < NN) {
                const float* src = sT + n * 132 + part * 32;
                float* dst = g_G + (size_t)gn * LDGG + m0 + part * 32;
                #pragma unroll
                for (int j = 0; j < 8; j++)
                    *(float4*)(dst + 4 * j) = *(const float4*)(src + 4 * j);
            }
        }
    }
}

// ---------------------------------------------------------------------------
// Edge GEMM: g_U = relu(P_i+R_j) @ W2.  grid (2, 1250), 256 thr.
// ---------------------------------------------------------------------------
__global__ void __launch_bounds__(256, 2) edge_mma_kernel() {
    extern __shared__ float smem_f[];
    float (*Ah)[SPAD] = (float(*)[SPAD])smem_f;
    float (*Al)[SPAD] = (float(*)[SPAD])(smem_f + 32 * SPAD);
    float* sBh = smem_f + 64 * SPAD;
    float* sBl = smem_f + 64 * SPAD + 4096;
    uint32_t uBh = (uint32_t)__cvta_generic_to_shared(sBh);
    uint32_t uBl = (uint32_t)__cvta_generic_to_shared(sBl);

    int t = threadIdx.x, lane = t & 31, wid = t >> 5;
    int wm = wid >> 2, wn = wid & 3;
    int m0 = blockIdx.y * 128;
    int nblk = 12 + blockIdx.x;
    int n0 = blockIdx.x * 128;

    float c[4][4][4];
    #pragma unroll
    for (int a = 0; a < 4; a++)
        #pragma unroll
        for (int b = 0; b < 4; b++)
            #pragma unroll
            for (int d = 0; d < 4; d++) c[a][b][d] = 0.f;

    int lr = t >> 1, lk = (t & 1) * 16;
    int e = m0 + lr;
    int inode = e >> 4;
    int jnode = g_nbr[e];
    const float* pp = g_NB + (size_t)inode * NBLD + 1024 + lk;
    const float* rp = g_NB + (size_t)jnode * NBLD + 1280 + lk;

    for (int chunk = 0; chunk < 8; chunk++) {
        size_t bB = ((size_t)nblk * 8 + chunk) * 4096;
        #pragma unroll
        for (int i = 0; i < 4; i++) {
            int f = t + i * 256;
            cpa16(uBh + (uint32_t)f * 16, g_WBh + bB + 4 * f);
            cpa16(uBl + (uint32_t)f * 16, g_WBl + bB + 4 * f);
        }
        CP_COMMIT();

        int k0 = chunk * 32;
        #pragma unroll
        for (int jj = 0; jj < 4; jj++) {
            float4 pv = *(const float4*)(pp + k0 + 4 * jj);
            float4 rv = *(const float4*)(rp + k0 + 4 * jj);
            float2 s0 = split_tf(fmaxf(pv.x + rv.x, 0.f));
            float2 s1 = split_tf(fmaxf(pv.y + rv.y, 0.f));
            float2 s2 = split_tf(fmaxf(pv.z + rv.z, 0.f));
            float2 s3 = split_tf(fmaxf(pv.w + rv.w, 0.f));
            int kk = lk + 4 * jj;
            Ah[kk + 0][lr] = s0.x; Ah[kk + 1][lr] = s1.x; Ah[kk + 2][lr] = s2.x; Ah[kk + 3][lr] = s3.x;
            Al[kk + 0][lr] = s0.y; Al[kk + 1][lr] = s1.y; Al[kk + 2][lr] = s2.y; Al[kk + 3][lr] = s3.y;
        }
        CP_WAIT0();
        __syncthreads();
        mma_chunk_cf(Ah, Al, sBh, sBl, wm, wn, lane, c);
        __syncthreads();
    }

    int r = lane >> 2, q = lane & 3;
    #pragma unroll
    for (int mf = 0; mf < 4; mf++) {
        #pragma unroll
        for (int nf = 0; nf < 4; nf++) {
            int row = m0 + wm * 64 + mf * 16 + r;
            int col = n0 + wn * 32 + nf * 8 + 2 * q;
            *(float2*)(g_U + (size_t)row * 256 + col) =
                make_float2(c[mf][nf][0], c[mf][nf][1]);
            *(float2*)(g_U + (size_t)(row + 8) * 256 + col) =
                make_float2(c[mf][nf][2], c[mf][nf][3]);
        }
    }
}

// ---------------------------------------------------------------------------
// Exact top-16 per row: per-thread top-2 superset + threshold gather.
// ---------------------------------------------------------------------------
__device__ __forceinline__ uint32_t fkey(float d) {
    uint32_t u = __float_as_uint(d);
    return u ^ ((u & 0x80000000u) ? 0xFFFFFFFFu : 0x80000000u);
}

__global__ void __launch_bounds__(256) topk_kernel() {
    extern __shared__ float sd[];                 // NN floats
    __shared__ u64 s_cand[512];
    __shared__ u64 s_buf[1024];
    __shared__ u64 s_T;
    __shared__ int s_cnt;

    int row = blockIdx.x, t = threadIdx.x, lane = t & 31;
    const float FINF = __int_as_float(0x7f800000);
    if (t == 0) s_cnt = 0;

    float n2i = g_n2[row];
    const float* Gr = g_G + (size_t)row * LDGG;

    // Phase 1: distances -> sd; per-thread top-2 (u64 keys, b0 <= b1)
    u64 b0 = ~0ull, b1 = ~0ull;
    #pragma unroll 2
    for (int it = 0; it < 10; it++) {
        int j0 = t * 4 + it * 1024;
        if (j0 < NN) {
            float4 g  = *(const float4*)(Gr + j0);
            float4 nn = *(const float4*)(g_n2 + j0);
            float d[4];
            d[0] = n2i + nn.x - 2.f * g.x;
            d[1] = n2i + nn.y - 2.f * g.y;
            d[2] = n2i + nn.z - 2.f * g.z;
            d[3] = n2i + nn.w - 2.f * g.w;
            #pragma unroll
            for (int e2 = 0; e2 < 4; e2++)
                if (j0 + e2 == row) d[e2] = FINF;
            *(float4*)&sd[j0] = make_float4(d[0], d[1], d[2], d[3]);
            #pragma unroll
            for (int e2 = 0; e2 < 4; e2++) {
                u64 key = ((u64)fkey(d[e2]) << 32) | (uint32_t)(j0 + e2);
                if (key < b1) {
                    if (key < b0) { b1 = b0; b0 = key; } else b1 = key;
                }
            }
        }
    }
    s_cand[2 * t]     = b0;
    s_cand[2 * t + 1] = b1;
    __syncthreads();

    // Phase 2: warp 0 finds the 16th smallest of the 512 candidates -> T
    if (t < 32) {
        for (int sel = 0; sel < 16; sel++) {
            u64 mv = ~0ull; int mi = -1;
            #pragma unroll
            for (int rr = 0; rr < 16; rr++) {
                int p = lane + 32 * rr;
                u64 v = s_cand[p];
                if (v < mv) { mv = v; mi = p; }
            }
            #pragma unroll
            for (int o = 16; o; o >>= 1) {
                u64 ov = __shfl_xor_sync(0xffffffffu, mv, o);
                int oi = __shfl_xor_sync(0xffffffffu, mi, o);
                if (ov < mv) { mv = ov; mi = oi; }
            }
            if (lane == 0) {
                if (sel == 15) s_T = mv;
                s_cand[mi] = ~0ull;
            }
            __syncwarp();
        }
    }
    __syncthreads();
    u64 T = s_T;

    // Phase 3: gather all keys <= T (superset of true top-16)
    #pragma unroll 2
    for (int it = 0; it < 10; it++) {
        int j0 = t * 4 + it * 1024;
        if (j0 < NN) {
            float4 dv = *(const float4*)&sd[j0];
            float d[4] = {dv.x, dv.y, dv.z, dv.w};
            #pragma unroll
            for (int e2 = 0; e2 < 4; e2++) {
                u64 key = ((u64)fkey(d[e2]) << 32) | (uint32_t)(j0 + e2);
                if (key <= T) {
                    int p = atomicAdd(&s_cnt, 1);
                    if (p < 1024) s_buf[p] = key;
                }
            }
        }
    }
    __syncthreads();
    int C = s_cnt;

    if (C <= 1024) {
        // Phase 4: exact select-16 from the (small) superset
        if (t < 32) {
            for (int sel = 0; sel < 16; sel++) {
                u64 mv = ~0ull; int mi = -1;
                for (int p = lane; p < C; p += 32) {
                    u64 v = s_buf[p];
                    if (v < mv) { mv = v; mi = p; }
                }
                #pragma unroll
                for (int o = 16; o; o >>= 1) {
                    u64 ov = __shfl_xor_sync(0xffffffffu, mv, o);
                    int oi = __shfl_xor_sync(0xffffffffu, mi, o);
                    if (ov < mv) { mv = ov; mi = oi; }
                }
                if (lane == 0) {
                    g_nbr[row * 16 + sel] = (int)(mv & 0xffffffffu);
                    s_buf[mi] = ~0ull;
                }
                __syncwarp();
            }
        }
    } else {
        // Fallback (unreachable on continuous data): exact 16x min-scan over sd
        if (t < 32) {
            for (int sel = 0; sel < 16; sel++) {
                u64 mv = ~0ull; int mi = -1;
                for (int j = lane; j < NN; j += 32) {
                    u64 v = ((u64)fkey(sd[j]) << 32) | (uint32_t)j;
                    if (v < mv) { mv = v; mi = j; }
                }
                #pragma unroll
                for (int o = 16; o; o >>= 1) {
                    u64 ov = __shfl_xor_sync(0xffffffffu, mv, o);
                    int oi = __shfl_xor_sync(0xffffffffu, mi, o);
                    if (ov < mv) { mv = ov; mi = oi; }
                }
                if (lane == 0) {
                    g_nbr[row * 16 + sel] = mi;
                    sd[mi] = FINF;
                }
                __syncwarp();
            }
        }
    }
}

// ---------------------------------------------------------------------------
// Combine: ew per edge + mixing + mean aggregation
// ---------------------------------------------------------------------------
__global__ void combine_kernel(float* __restrict__ out) {
    int i = blockIdx.x;
    int t = threadIdx.x;
    __shared__ float qb[256], kb[256], sb[256], ewsh[4];

    const float* nbi = g_NB + (size_t)i * NBLD;
    for (int c = t; c < 256; c += 128) {
        qb[c] = nbi[256 + c];
        kb[c] = nbi[768 + c];
        sb[c] = nbi[1536 + c];
    }
    __syncthreads();

    int w    = t >> 5;
    int lane = t & 31;
    int h = w >> 1, g = w & 1;

    float a0 = 0.f, a1 = 0.f;

    for (int kk = 0; kk < 16; kk++) {
        int e = i * 16 + kk;
        int j = g_nbr[e];
        const float* qaj = g_NB + (size_t)j * NBLD;
        const float* kaj = qaj + 512;
        float s = 0.f;
        #pragma unroll
        for (int r = 0; r < 4; r++) {
            int d = lane + 32 * r;
            float qv = qaj[h * 128 + d] + qb[h * 128 + d];
            float kv = kaj[g * 128 + d] + kb[g * 128 + d];
            s = fmaf(qv, kv, s);
        }
        #pragma unroll
        for (int o = 16; o; o >>= 1) s += __shfl_xor_sync(0xffffffffu, s, o);
        if (lane == 0) ewsh[w] = s * 0.0625f;
        __syncthreads();
        float e00 = ewsh[0], e01 = ewsh[1], e10 = ewsh[2], e11 = ewsh[3];
        float2 u2 = *(const float2*)&g_U[(size_t)e * 256 + 2 * t];
        float u0 = u2.x + sb[2 * t];
        float u1 = u2.y + sb[2 * t + 1];
        a0 += u0 * e00 + u1 * e10;
        a1 += u0 * e01 + u1 * e11;
        __syncthreads();
    }

    out[(size_t)i * 256 + 2 * t]     = a0 * 0.0625f;
    out[(size_t)i * 256 + 2 * t + 1] = a1 * 0.0625f;
}

// ---------------------------------------------------------------------------
// Launch (topk in profile slot 4)
// ---------------------------------------------------------------------------
extern "C" void kernel_launch(void* const* d_in, const int* in_sizes, int n_in,
                              void* d_out, int out_size) {
    const float* x  = (const float*)d_in[0];
    const float* W1 = (const float*)d_in[1];
    const float* b1 = (const float*)d_in[2];
    const float* W2 = (const float*)d_in[3];
    const float* b2 = (const float*)d_in[4];
    const float* Wq = (const float*)d_in[5];
    const float* bq = (const float*)d_in[6];
    const float* Wk = (const float*)d_in[7];
    const float* bk = (const float*)d_in[8];
    float* out = (float*)d_out;

    const int GEMM_SMEM = 16384 * (int)sizeof(float);             // 65536
    const int EDGE_SMEM = (64 * SPAD + 8192) * (int)sizeof(float);// 67584
    const int TOPK_SMEM = NN * (int)sizeof(float);                // 40000
    cudaFuncSetAttribute(node_mma_kernel, cudaFuncAttributeMaxDynamicSharedMemorySize, GEMM_SMEM);
    cudaFuncSetAttribute(gram_mma_kernel, cudaFuncAttributeMaxDynamicSharedMemorySize, GEMM_SMEM);
    cudaFuncSetAttribute(edge_mma_kernel, cudaFuncAttributeMaxDynamicSharedMemorySize, EDGE_SMEM);
    cudaFuncSetAttribute(topk_kernel,     cudaFuncAttributeMaxDynamicSharedMemorySize, TOPK_SMEM);

    xfrag_kernel<<<dim3(8, NBLK), 256>>>(x);                      // 1
    norms_kernel<<<1250, 256>>>(x);                               // 2
    gram_mma_kernel<<<dim3(79, 79), 256, GEMM_SMEM>>>();          // 3
    topk_kernel<<<NN, 256, TOPK_SMEM>>>();                        // 4  <- profiled
    wfrag_kernel<<<dim3(8, 14), 256>>>(Wq, Wk, W1, W2);           // 5
    build_bias_kernel<<<7, 256>>>(bq, bk, b1, b2);                // 6
    node_mma_kernel<<<dim3(14, 79), 256, GEMM_SMEM>>>();          // 7
    edge_mma_kernel<<<dim3(2, 1250), 256, EDGE_SMEM>>>();         // 8
    combine_kernel<<<NN, 128>>>(out);                             // 9
}

// round 17
// speedup vs baseline: 1.0595x; 1.0595x over previous
#include <cuda_runtime.h>
#include <cstdint>
#include <cstddef>

#define NN    10000
#define KNBR  16
#define LDGG  10016
#define NBLD  1792
#define EE    (NN*KNBR)

#define NBLK  79
#define SPAD  136
typedef unsigned long long u64;

// Fragment-major global arrays (layouts documented in R10).
static __device__ float g_xAh[(size_t)NBLK * 32768];
static __device__ float g_xAl[(size_t)NBLK * 32768];
static __device__ float g_xBh[(size_t)NBLK * 32768];
static __device__ float g_xBl[(size_t)NBLK * 32768];
static __device__ float g_WBh[(size_t)14 * 32768];
static __device__ float g_WBl[(size_t)14 * 32768];

static __device__ float g_G[(size_t)NN * LDGG];
static __device__ float g_NB[(size_t)NN * NBLD];     // 0:Qa 1:Qb(+bq) 2:Ka 3:Kb(+bk) 4:P(+b1) 5:R 6:S(+b2)
static __device__ float g_bias[NBLD];
static __device__ float g_n2[NN];
static __device__ int   g_nbr[EE];
static __device__ float g_U[(size_t)EE * 256];

// ---------------------------------------------------------------------------
// helpers
// ---------------------------------------------------------------------------
__device__ __forceinline__ uint32_t f2tf(float v) {
    uint32_t u; asm("cvt.rna.tf32.f32 %0, %1;" : "=r"(u) : "f"(v)); return u;
}
__device__ __forceinline__ float2 split_tf(float v) {
    uint32_t hi = f2tf(v);
    uint32_t lo = f2tf(v - __uint_as_float(hi));
    return make_float2(__uint_as_float(hi), __uint_as_float(lo));
}
__device__ __forceinline__ void mma8(float c[4], const uint32_t a[4], uint32_t b0, uint32_t b1) {
    asm volatile(
        "mma.sync.aligned.m16n8k8.row.col.f32.tf32.tf32.f32 "
        "{%0,%1,%2,%3}, {%4,%5,%6,%7}, {%8,%9}, {%0,%1,%2,%3};"
        : "+f"(c[0]), "+f"(c[1]), "+f"(c[2]), "+f"(c[3])
        : "r"(a[0]), "r"(a[1]), "r"(a[2]), "r"(a[3]), "r"(b0), "r"(b1));
}
#define FU(x) __float_as_uint(x)

__device__ __forceinline__ void cpa16(uint32_t dst, const void* src) {
    asm volatile("cp.async.cg.shared.global [%0], [%1], 16;" :: "r"(dst), "l"(src));
}
#define CP_COMMIT() asm volatile("cp.async.commit_group;" ::: "memory")
#define CP_WAIT0()  asm volatile("cp.async.wait_group 0;" ::: "memory")

// K=16 stage, both operands fragment-major (2048 floats per array per stage).
__device__ __forceinline__ void mma_stage_ff(
    const float* sAh, const float* sAl, const float* sBh, const float* sBl,
    int a4base, int b2base, int wm, int wn, int lane, float c[4][4][4]) {
    #pragma unroll
    for (int kc = 0; kc < 2; kc++) {
        float2 bh[4], bl[4];
        #pragma unroll
        for (int nf = 0; nf < 4; nf++) {
            int bi = b2base + (kc * 16 + wn * 4 + nf) * 32 + lane;
            bh[nf] = ((const float2*)sBh)[bi];
            bl[nf] = ((const float2*)sBl)[bi];
        }
        #pragma unroll
        for (int mf = 0; mf < 4; mf++) {
            int ai = a4base + (kc * 8 + wm * 4 + mf) * 32 + lane;
            float4 vh = ((const float4*)sAh)[ai];
            float4 vl = ((const float4*)sAl)[ai];
            uint32_t ah[4] = {FU(vh.x), FU(vh.y), FU(vh.z), FU(vh.w)};
            uint32_t al[4] = {FU(vl.x), FU(vl.y), FU(vl.z), FU(vl.w)};
            #pragma unroll
            for (int nf = 0; nf < 4; nf++) {
                mma8(c[mf][nf], ah, FU(bh[nf].x), FU(bh[nf].y));
                mma8(c[mf][nf], al, FU(bh[nf].x), FU(bh[nf].y));
                mma8(c[mf][nf], ah, FU(bl[nf].x), FU(bl[nf].y));
            }
        }
    }
}

// K=32 chunk, A classic [k][m+SPAD], B fragment-major (edge kernel).
__device__ __forceinline__ void mma_chunk_cf(
    const float (*Ah)[SPAD], const float (*Al)[SPAD],
    const float* sBh, const float* sBl,
    int wm, int wn, int lane, float c[4][4][4]) {
    int r = lane >> 2, cl = lane & 3;
    #pragma unroll
    for (int kc = 0; kc < 4; kc++) {
        float2 bh[4], bl[4];
        #pragma unroll
        for (int nf = 0; nf < 4; nf++) {
            int bi = (kc * 16 + wn * 4 + nf) * 32 + lane;
            bh[nf] = ((const float2*)sBh)[bi];
            bl[nf] = ((const float2*)sBl)[bi];
        }
        int k0 = kc * 8;
        #pragma unroll
        for (int mf = 0; mf < 4; mf++) {
            int rb = wm * 64 + mf * 16 + r;
            uint32_t ah[4] = {FU(Ah[k0 + cl][rb]),     FU(Ah[k0 + cl][rb + 8]),
                              FU(Ah[k0 + cl + 4][rb]), FU(Ah[k0 + cl + 4][rb + 8])};
            uint32_t al[4] = {FU(Al[k0 + cl][rb]),     FU(Al[k0 + cl][rb + 8]),
                              FU(Al[k0 + cl + 4][rb]), FU(Al[k0 + cl + 4][rb + 8])};
            #pragma unroll
            for (int nf = 0; nf < 4; nf++) {
                mma8(c[mf][nf], ah, FU(bh[nf].x), FU(bh[nf].y));
                mma8(c[mf][nf], al, FU(bh[nf].x), FU(bh[nf].y));
                mma8(c[mf][nf], ah, FU(bl[nf].x), FU(bl[nf].y));
            }
        }
    }
}

// ---------------------------------------------------------------------------
// Pre-transform x -> fragment-major A and B layouts (hi/lo).  grid (8, 79).
// ---------------------------------------------------------------------------
__global__ void xfrag_kernel(const float* __restrict__ x) {
    __shared__ float sh[32][129];
    __shared__ float sl[32][129];
    int blk = blockIdx.y, chunk = blockIdx.x, t = threadIdx.x;

    #pragma unroll
    for (int i = 0; i < 4; i++) {
        int idx = t + i * 256;
        int m  = idx >> 3;
        int kq = (idx & 7) * 4;
        int row = blk * 128 + m; if (row >= NN) row = NN - 1;
        float4 v = *(const float4*)(x + (size_t)row * 256 + chunk * 32 + kq);
        float2 s0 = split_tf(v.x), s1 = split_tf(v.y), s2 = split_tf(v.z), s3 = split_tf(v.w);
        sh[kq + 0][m] = s0.x; sh[kq + 1][m] = s1.x; sh[kq + 2][m] = s2.x; sh[kq + 3][m] = s3.x;
        sl[kq + 0][m] = s0.y; sl[kq + 1][m] = s1.y; sl[kq + 2][m] = s2.y; sl[kq + 3][m] = s3.y;
    }
    __syncthreads();

    size_t base = ((size_t)blk * 8 + chunk) * 4096;
    #pragma unroll
    for (int i = 0; i < 16; i++) {
        int o = t + i * 256;
        int reg = o & 3, lane = (o >> 2) & 31, wmmf = (o >> 7) & 7, kc = o >> 10;
        int r = lane >> 2, cl = lane & 3, half = reg >> 1, sel = reg & 1;
        int k = kc * 8 + half * 4 + cl;
        int m = wmmf * 16 + sel * 8 + r;
        g_xAh[base + o] = sh[k][m];
        g_xAl[base + o] = sl[k][m];
        int regb = o & 1, laneb = (o >> 1) & 31, wnnf = (o >> 6) & 15, kcb = o >> 10;
        int rb2 = laneb >> 2, clb = laneb & 3;
        int kb = kcb * 8 + regb * 4 + clb;
        int nb = wnnf * 8 + rb2;
        g_xBh[base + o] = sh[kb][nb];
        g_xBl[base + o] = sl[kb][nb];
    }
}

// ---------------------------------------------------------------------------
// Pre-transform Wcat^T -> fragment-major B layout.  grid (8, 14).
// ---------------------------------------------------------------------------
__global__ void wfrag_kernel(const float* __restrict__ Wq,
                             const float* __restrict__ Wk,
                             const float* __restrict__ W1,
                             const float* __restrict__ W2) {
    __shared__ float sh[32][129];
    __shared__ float sl[32][129];
    int nblk = blockIdx.y, chunk = blockIdx.x, t = threadIdx.x;
    int b = nblk >> 1;
    int cbase = (nblk & 1) * 128;

    #pragma unroll
    for (int i = 0; i < 4; i++) {
        int idx = t + i * 256;
        int kk = idx >> 5;
        int n4 = (idx & 31) * 4;
        int k = chunk * 32 + kk;
        int c = cbase + n4;
        const float* src;
        switch (b) {
            case 0: src = Wq + (size_t)k * 256 + c;         break;
            case 1: src = Wq + (size_t)(k + 256) * 256 + c; break;
            case 2: src = Wk + (size_t)k * 256 + c;         break;
            case 3: src = Wk + (size_t)(k + 256) * 256 + c; break;
            case 4: src = W1 + (size_t)k * 256 + c;         break;
            case 5: src = W1 + (size_t)(k + 256) * 256 + c; break;
            default: src = W2 + (size_t)k * 256 + c;        break;
        }
        float4 v = *(const float4*)src;
        float2 s0 = split_tf(v.x), s1 = split_tf(v.y), s2 = split_tf(v.z), s3 = split_tf(v.w);
        sh[kk][n4 + 0] = s0.x; sh[kk][n4 + 1] = s1.x; sh[kk][n4 + 2] = s2.x; sh[kk][n4 + 3] = s3.x;
        sl[kk][n4 + 0] = s0.y; sl[kk][n4 + 1] = s1.y; sl[kk][n4 + 2] = s2.y; sl[kk][n4 + 3] = s3.y;
    }
    __syncthreads();

    size_t base = ((size_t)nblk * 8 + chunk) * 4096;
    #pragma unroll
    for (int i = 0; i < 16; i++) {
        int o = t + i * 256;
        int reg = o & 1, lane = (o >> 1) & 31, wnnf = (o >> 6) & 15, kc = o >> 10;
        int r = lane >> 2, cl = lane & 3;
        int k = kc * 8 + reg * 4 + cl;
        int n = wnnf * 8 + r;
        g_WBh[base + o] = sh[k][n];
        g_WBl[base + o] = sl[k][n];
    }
}

__global__ void build_bias_kernel(const float* __restrict__ bq,
                                  const float* __restrict__ bk,
                                  const float* __restrict__ b1,
                                  const float* __restrict__ b2) {
    int n = blockIdx.x * 256 + threadIdx.x;
    int b = n >> 8, c = n & 255;
    float v = 0.f;
    if (b == 1) v = bq[c];
    else if (b == 3) v = bk[c];
    else if (b == 4) v = b1[c];
    else if (b == 6) v = b2[c];
    g_bias[n] = v;
}

__global__ void norms_kernel(const float* __restrict__ x) {
    int row  = blockIdx.x * 8 + (threadIdx.x >> 5);
    int lane = threadIdx.x & 31;
    const float4* xr = (const float4*)(x + (size_t)row * 256);
    float s = 0.f;
    #pragma unroll
    for (int r = 0; r < 2; r++) {
        float4 v = xr[lane + 32 * r];
        s += v.x * v.x + v.y * v.y + v.z * v.z + v.w * v.w;
    }
    #pragma unroll
    for (int o = 16; o; o >>= 1) s += __shfl_xor_sync(0xffffffffu, s, o);
    if (lane == 0) g_n2[row] = s;
}

// ---------------------------------------------------------------------------
// Pipelined staging
// ---------------------------------------------------------------------------
__device__ __forceinline__ void stage_issue(
    uint32_t uAh, uint32_t uAl, uint32_t uBh, uint32_t uBl,
    const float* gAh, const float* gAl, const float* gBh, const float* gBl,
    size_t aB, size_t bB, int buf, int t) {
    #pragma unroll
    for (int i = 0; i < 2; i++) {
        int f = t + i * 256;
        uint32_t doff = (uint32_t)(buf * 512 + f) * 16;
        cpa16(uAh + doff, gAh + aB + 4 * f);
        cpa16(uAl + doff, gAl + aB + 4 * f);
        cpa16(uBh + doff, gBh + bB + 4 * f);
        cpa16(uBl + doff, gBl + bB + 4 * f);
    }
    CP_COMMIT();
}

// ---------------------------------------------------------------------------
// Node GEMM: g_NB = x @ Wcat + bias.  grid (14, 79), 256 thr, smem 64 KB.
// ---------------------------------------------------------------------------
__global__ void __launch_bounds__(256, 2) node_mma_kernel() {
    extern __shared__ float smem_f[];
    float* sAh = smem_f;
    float* sAl = smem_f + 4096;
    float* sBh = smem_f + 8192;
    float* sBl = smem_f + 12288;
    uint32_t uAh = (uint32_t)__cvta_generic_to_shared(sAh);
    uint32_t uAl = (uint32_t)__cvta_generic_to_shared(sAl);
    uint32_t uBh = (uint32_t)__cvta_generic_to_shared(sBh);
    uint32_t uBl = (uint32_t)__cvta_generic_to_shared(sBl);

    int t = threadIdx.x, lane = t & 31, wid = t >> 5;
    int wm = wid >> 2, wn = wid & 3;
    int m0 = blockIdx.y * 128, n0 = blockIdx.x * 128;
    size_t aBase = (size_t)blockIdx.y * 32768;
    size_t bBase = (size_t)blockIdx.x * 32768;

    float c[4][4][4];
    #pragma unroll
    for (int a = 0; a < 4; a++)
        #pragma unroll
        for (int b = 0; b < 4; b++)
            #pragma unroll
            for (int d = 0; d < 4; d++) c[a][b][d] = 0.f;

    stage_issue(uAh, uAl, uBh, uBl, g_xAh, g_xAl, g_WBh, g_WBl, aBase, bBase, 0, t);
    for (int cs = 0; cs < 16; cs++) {
        int buf = cs & 1;
        CP_WAIT0();
        __syncthreads();
        if (cs < 15)
            stage_issue(uAh, uAl, uBh, uBl, g_xAh, g_xAl, g_WBh, g_WBl,
                        aBase + (cs + 1) * 2048, bBase + (cs + 1) * 2048, buf ^ 1, t);
        mma_stage_ff(sAh, sAl, sBh, sBl, buf * 512, buf * 1024, wm, wn, lane, c);
        __syncthreads();
    }

    int r = lane >> 2, q = lane & 3;
    #pragma unroll
    for (int mf = 0; mf < 4; mf++) {
        #pragma unroll
        for (int nf = 0; nf < 4; nf++) {
            int row = m0 + wm * 64 + mf * 16 + r;
            int col = n0 + wn * 32 + nf * 8 + 2 * q;
            float b0 = g_bias[col], b1 = g_bias[col + 1];
            if (row < NN)
                *(float2*)(g_NB + (size_t)row * NBLD + col) =
                    make_float2(c[mf][nf][0] + b0, c[mf][nf][1] + b1);
            if (row + 8 < NN)
                *(float2*)(g_NB + (size_t)(row + 8) * NBLD + col) =
                    make_float2(c[mf][nf][2] + b0, c[mf][nf][3] + b1);
        }
    }
}

// ---------------------------------------------------------------------------
// Gram: G = x @ x^T, upper tiles + mirror.  grid (79, 79), 256 thr.
// ---------------------------------------------------------------------------
__global__ void __launch_bounds__(256, 2) gram_mma_kernel() {
    if (blockIdx.x < blockIdx.y) return;
    extern __shared__ float smem_f[];
    float* sAh = smem_f;
    float* sAl = smem_f + 4096;
    float* sBh = smem_f + 8192;
    float* sBl = smem_f + 12288;
    uint32_t uAh = (uint32_t)__cvta_generic_to_shared(sAh);
    uint32_t uAl = (uint32_t)__cvta_generic_to_shared(sAl);
    uint32_t uBh = (uint32_t)__cvta_generic_to_shared(sBh);
    uint32_t uBl = (uint32_t)__cvta_generic_to_shared(sBl);

    int t = threadIdx.x, lane = t & 31, wid = t >> 5;
    int wm = wid >> 2, wn = wid & 3;
    int m0 = blockIdx.y * 128, n0 = blockIdx.x * 128;
    bool diag = (blockIdx.x == blockIdx.y);
    size_t aBase = (size_t)blockIdx.y * 32768;
    size_t bBase = (size_t)blockIdx.x * 32768;

    float c[4][4][4];
    #pragma unroll
    for (int a = 0; a < 4; a++)
        #pragma unroll
        for (int b = 0; b < 4; b++)
            #pragma unroll
            for (int d = 0; d < 4; d++) c[a][b][d] = 0.f;

    stage_issue(uAh, uAl, uBh, uBl, g_xAh, g_xAl, g_xBh, g_xBl, aBase, bBase, 0, t);
    for (int cs = 0; cs < 16; cs++) {
        int buf = cs & 1;
        CP_WAIT0();
        __syncthreads();
        if (cs < 15)
            stage_issue(uAh, uAl, uBh, uBl, g_xAh, g_xAl, g_xBh, g_xBl,
                        aBase + (cs + 1) * 2048, bBase + (cs + 1) * 2048, buf ^ 1, t);
        mma_stage_ff(sAh, sAl, sBh, sBl, buf * 512, buf * 1024, wm, wn, lane, c);
        __syncthreads();
    }

    int r = lane >> 2, q = lane & 3;
    // direct store (upper tile)
    #pragma unroll
    for (int mf = 0; mf < 4; mf++) {
        #pragma unroll
        for (int nf = 0; nf < 4; nf++) {
            int row = m0 + wm * 64 + mf * 16 + r;
            int col = n0 + wn * 32 + nf * 8 + 2 * q;
            if (col + 1 < NN) {
                if (row < NN)
                    *(float2*)(g_G + (size_t)row * LDGG + col) =
                        make_float2(c[mf][nf][0], c[mf][nf][1]);
                if (row + 8 < NN)
                    *(float2*)(g_G + (size_t)(row + 8) * LDGG + col) =
                        make_float2(c[mf][nf][2], c[mf][nf][3]);
            } else if (col < NN) {
                if (row < NN)     g_G[(size_t)row * LDGG + col]       = c[mf][nf][0];
                if (row + 8 < NN) g_G[(size_t)(row + 8) * LDGG + col] = c[mf][nf][2];
            }
        }
    }

    // mirror store (off-diag)
    if (!diag) {
        float* sT = smem_f;
        for (int h = 0; h < 2; h++) {
            __syncthreads();
            if ((wn >> 1) == h) {
                #pragma unroll
                for (int mf = 0; mf < 4; mf++) {
                    #pragma unroll
                    for (int nf = 0; nf < 4; nf++) {
                        int rowl = wm * 64 + mf * 16 + r;
                        int cn   = (wn & 1) * 32 + nf * 8 + 2 * q;
                        sT[cn * 132 + rowl]           = c[mf][nf][0];
                        sT[(cn + 1) * 132 + rowl]     = c[mf][nf][1];
                        sT[cn * 132 + rowl + 8]       = c[mf][nf][2];
                        sT[(cn + 1) * 132 + rowl + 8] = c[mf][nf][3];
                    }
                }
            }
            __syncthreads();
            int n    = t >> 2;
            int part = t & 3;
            int gn = n0 + h * 64 + n;
            if (gn < NN) {
                const float* src = sT + n * 132 + part * 32;
                float* dst = g_G + (size_t)gn * LDGG + m0 + part * 32;
                #pragma unroll
                for (int j = 0; j < 8; j++)
                    *(float4*)(dst + 4 * j) = *(const float4*)(src + 4 * j);
            }
        }
    }
}

// ---------------------------------------------------------------------------
// Edge GEMM: g_U = relu(P_i+R_j) @ W2.  grid (2, 1250), 256 thr.
// ---------------------------------------------------------------------------
__global__ void __launch_bounds__(256, 2) edge_mma_kernel() {
    extern __shared__ float smem_f[];
    float (*Ah)[SPAD] = (float(*)[SPAD])smem_f;
    float (*Al)[SPAD] = (float(*)[SPAD])(smem_f + 32 * SPAD);
    float* sBh = smem_f + 64 * SPAD;
    float* sBl = smem_f + 64 * SPAD + 4096;
    uint32_t uBh = (uint32_t)__cvta_generic_to_shared(sBh);
    uint32_t uBl = (uint32_t)__cvta_generic_to_shared(sBl);

    int t = threadIdx.x, lane = t & 31, wid = t >> 5;
    int wm = wid >> 2, wn = wid & 3;
    int m0 = blockIdx.y * 128;
    int nblk = 12 + blockIdx.x;
    int n0 = blockIdx.x * 128;

    float c[4][4][4];
    #pragma unroll
    for (int a = 0; a < 4; a++)
        #pragma unroll
        for (int b = 0; b < 4; b++)
            #pragma unroll
            for (int d = 0; d < 4; d++) c[a][b][d] = 0.f;

    int lr = t >> 1, lk = (t & 1) * 16;
    int e = m0 + lr;
    int inode = e >> 4;
    int jnode = g_nbr[e];
    jnode = (jnode < 0) ? 0 : ((jnode >= NN) ? (NN - 1) : jnode);   // safety clamp
    const float* pp = g_NB + (size_t)inode * NBLD + 1024 + lk;
    const float* rp = g_NB + (size_t)jnode * NBLD + 1280 + lk;

    for (int chunk = 0; chunk < 8; chunk++) {
        size_t bB = ((size_t)nblk * 8 + chunk) * 4096;
        #pragma unroll
        for (int i = 0; i < 4; i++) {
            int f = t + i * 256;
            cpa16(uBh + (uint32_t)f * 16, g_WBh + bB + 4 * f);
            cpa16(uBl + (uint32_t)f * 16, g_WBl + bB + 4 * f);
        }
        CP_COMMIT();

        int k0 = chunk * 32;
        #pragma unroll
        for (int jj = 0; jj < 4; jj++) {
            float4 pv = *(const float4*)(pp + k0 + 4 * jj);
            float4 rv = *(const float4*)(rp + k0 + 4 * jj);
            float2 s0 = split_tf(fmaxf(pv.x + rv.x, 0.f));
            float2 s1 = split_tf(fmaxf(pv.y + rv.y, 0.f));
            float2 s2 = split_tf(fmaxf(pv.z + rv.z, 0.f));
            float2 s3 = split_tf(fmaxf(pv.w + rv.w, 0.f));
            int kk = lk + 4 * jj;
            Ah[kk + 0][lr] = s0.x; Ah[kk + 1][lr] = s1.x; Ah[kk + 2][lr] = s2.x; Ah[kk + 3][lr] = s3.x;
            Al[kk + 0][lr] = s0.y; Al[kk + 1][lr] = s1.y; Al[kk + 2][lr] = s2.y; Al[kk + 3][lr] = s3.y;
        }
        CP_WAIT0();
        __syncthreads();
        mma_chunk_cf(Ah, Al, sBh, sBl, wm, wn, lane, c);
        __syncthreads();
    }

    int r = lane >> 2, q = lane & 3;
    #pragma unroll
    for (int mf = 0; mf < 4; mf++) {
        #pragma unroll
        for (int nf = 0; nf < 4; nf++) {
            int row = m0 + wm * 64 + mf * 16 + r;
            int col = n0 + wn * 32 + nf * 8 + 2 * q;
            *(float2*)(g_U + (size_t)row * 256 + col) =
                make_float2(c[mf][nf][0], c[mf][nf][1]);
            *(float2*)(g_U + (size_t)(row + 8) * 256 + col) =
                make_float2(c[mf][nf][2], c[mf][nf][3]);
        }
    }
}

// ---------------------------------------------------------------------------
// Exact top-16 per row: float-only per-thread top-2 superset + keyed gather.
// Anomalies (C<16 or C>1024 or mi<0 — provably impossible) route to the
// exact NN-scan fallback; no crash-capable writes remain.
// ---------------------------------------------------------------------------
__device__ __forceinline__ uint32_t fkey(float d) {
    uint32_t u = __float_as_uint(d);
    return u ^ ((u & 0x80000000u) ? 0xFFFFFFFFu : 0x80000000u);
}

__global__ void __launch_bounds__(256) topk_kernel() {
    extern __shared__ float sd[];                 // NN floats
    __shared__ float s_cand[512];
    __shared__ u64 s_buf[1024];
    __shared__ float s_T;
    __shared__ int s_cnt;

    int row = blockIdx.x, t = threadIdx.x, lane = t & 31;
    const float FINF = __int_as_float(0x7f800000);
    if (t == 0) { s_cnt = 0; s_T = FINF; }

    float n2i = g_n2[row];
    const float* Gr = g_G + (size_t)row * LDGG;

    // Phase 1: distances -> sd; per-thread top-2 as plain floats
    float b0 = FINF, b1 = FINF;
    #pragma unroll 2
    for (int it = 0; it < 10; it++) {
        int j0 = t * 4 + it * 1024;
        if (j0 < NN) {
            float4 g  = *(const float4*)(Gr + j0);
            float4 nn = *(const float4*)(g_n2 + j0);
            float d[4];
            d[0] = n2i + nn.x - 2.f * g.x;
            d[1] = n2i + nn.y - 2.f * g.y;
            d[2] = n2i + nn.z - 2.f * g.z;
            d[3] = n2i + nn.w - 2.f * g.w;
            #pragma unroll
            for (int e2 = 0; e2 < 4; e2++)
                if (j0 + e2 == row) d[e2] = FINF;
            *(float4*)&sd[j0] = make_float4(d[0], d[1], d[2], d[3]);
            #pragma unroll
            for (int e2 = 0; e2 < 4; e2++) {
                float v = d[e2];
                if (v < b1) {
                    if (v < b0) { b1 = b0; b0 = v; } else b1 = v;
                }
            }
        }
    }
    s_cand[2 * t]     = b0;
    s_cand[2 * t + 1] = b1;
    __syncthreads();

    // Phase 2: warp 0 finds 16th-smallest float of the 512 candidates -> T
    if (t < 32) {
        for (int sel = 0; sel < 16; sel++) {
            float mv = FINF; int mi = -1;
            #pragma unroll
            for (int rr = 0; rr < 16; rr++) {
                int p = lane + 32 * rr;
                float v = s_cand[p];
                if (v < mv) { mv = v; mi = p; }
            }
            #pragma unroll
            for (int o = 16; o; o >>= 1) {
                float ov = __shfl_xor_sync(0xffffffffu, mv, o);
                int oi = __shfl_xor_sync(0xffffffffu, mi, o);
                if (ov < mv) { mv = ov; mi = oi; }
            }
            if (lane == 0) {
                if (sel == 15) s_T = mv;
                if (mi >= 0 && mi < 512) s_cand[mi] = FINF;
            }
            __syncwarp();
        }
    }
    __syncthreads();
    float T = s_T;

    // Phase 3: gather keys for all d <= T (superset of true top-16)
    #pragma unroll 2
    for (int it = 0; it < 10; it++) {
        int j0 = t * 4 + it * 1024;
        if (j0 < NN) {
            float4 dv = *(const float4*)&sd[j0];
            float d[4] = {dv.x, dv.y, dv.z, dv.w};
            #pragma unroll
            for (int e2 = 0; e2 < 4; e2++) {
                if (d[e2] <= T) {
                    int p = atomicAdd(&s_cnt, 1);
                    if (p >= 0 && p < 1024)
                        s_buf[p] = ((u64)fkey(d[e2]) << 32) | (uint32_t)(j0 + e2);
                }
            }
        }
    }
    __syncthreads();
    int C = s_cnt;

    if (C >= 16 && C <= 1024) {
        // Phase 4: exact select-16 from the (small) superset
        if (t < 32) {
            for (int sel = 0; sel < 16; sel++) {
                u64 mv = ~0ull; int mi = -1;
                for (int p = lane; p < C; p += 32) {
                    u64 v = s_buf[p];
                    if (v < mv) { mv = v; mi = p; }
                }
                #pragma unroll
                for (int o = 16; o; o >>= 1) {
                    u64 ov = __shfl_xor_sync(0xffffffffu, mv, o);
                    int oi = __shfl_xor_sync(0xffffffffu, mi, o);
                    if (ov < mv) { mv = ov; mi = oi; }
                }
                if (lane == 0) {
                    int idx = (int)(mv & 0xffffffffu);
                    g_nbr[row * 16 + sel] = (idx >= 0 && idx < NN) ? idx : 0;
                    if (mi >= 0 && mi < 1024) s_buf[mi] = ~0ull;
                }
                __syncwarp();
            }
        }
    } else {
        // Fallback: exact 16x min-scan over sd (crash-free, always correct)
        if (t < 32) {
            for (int sel = 0; sel < 16; sel++) {
                u64 mv = ~0ull; int mi = 0;
                for (int j = lane; j < NN; j += 32) {
                    u64 v = ((u64)fkey(sd[j]) << 32) | (uint32_t)j;
                    if (v < mv) { mv = v; mi = j; }
                }
                #pragma unroll
                for (int o = 16; o; o >>= 1) {
                    u64 ov = __shfl_xor_sync(0xffffffffu, mv, o);
                    int oi = __shfl_xor_sync(0xffffffffu, mi, o);
                    if (ov < mv) { mv = ov; mi = oi; }
                }
                if (lane == 0) {
                    g_nbr[row * 16 + sel] = mi;
                    sd[mi] = FINF;
                }
                __syncwarp();
            }
        }
    }
}

// ---------------------------------------------------------------------------
// Combine: ew per edge + mixing + mean aggregation
// ---------------------------------------------------------------------------
__global__ void combine_kernel(float* __restrict__ out) {
    int i = blockIdx.x;
    int t = threadIdx.x;
    __shared__ float qb[256], kb[256], sb[256], ewsh[4];

    const float* nbi = g_NB + (size_t)i * NBLD;
    for (int c = t; c < 256; c += 128) {
        qb[c] = nbi[256 + c];
        kb[c] = nbi[768 + c];
        sb[c] = nbi[1536 + c];
    }
    __syncthreads();

    int w    = t >> 5;
    int lane = t & 31;
    int h = w >> 1, g = w & 1;

    float a0 = 0.f, a1 = 0.f;

    for (int kk = 0; kk < 16; kk++) {
        int e = i * 16 + kk;
        int j = g_nbr[e];
        j = (j < 0) ? 0 : ((j >= NN) ? (NN - 1) : j);   // safety clamp
        const float* qaj = g_NB + (size_t)j * NBLD;
        const float* kaj = qaj + 512;
        float s = 0.f;
        #pragma unroll
        for (int r = 0; r < 4; r++) {
            int d = lane + 32 * r;
            float qv = qaj[h * 128 + d] + qb[h * 128 + d];
            float kv = kaj[g * 128 + d] + kb[g * 128 + d];
            s = fmaf(qv, kv, s);
        }
        #pragma unroll
        for (int o = 16; o; o >>= 1) s += __shfl_xor_sync(0xffffffffu, s, o);
        if (lane == 0) ewsh[w] = s * 0.0625f;
        __syncthreads();
        float e00 = ewsh[0], e01 = ewsh[1], e10 = ewsh[2], e11 = ewsh[3];
        float2 u2 = *(const float2*)&g_U[(size_t)e * 256 + 2 * t];
        float u0 = u2.x + sb[2 * t];
        float u1 = u2.y + sb[2 * t + 1];
        a0 += u0 * e00 + u1 * e10;
        a1 += u0 * e01 + u1 * e11;
        __syncthreads();
    }

    out[(size_t)i * 256 + 2 * t]     = a0 * 0.0625f;
    out[(size_t)i * 256 + 2 * t + 1] = a1 * 0.0625f;
}

// ---------------------------------------------------------------------------
// Launch (topk in profile slot 4)
// ---------------------------------------------------------------------------
extern "C" void kernel_launch(void* const* d_in, const int* in_sizes, int n_in,
                              void* d_out, int out_size) {
    const float* x  = (const float*)d_in[0];
    const float* W1 = (const float*)d_in[1];
    const float* b1 = (const float*)d_in[2];
    const float* W2 = (const float*)d_in[3];
    const float* b2 = (const float*)d_in[4];
    const float* Wq = (const float*)d_in[5];
    const float* bq = (const float*)d_in[6];
    const float* Wk = (const float*)d_in[7];
    const float* bk = (const float*)d_in[8];
    float* out = (float*)d_out;

    const int GEMM_SMEM = 16384 * (int)sizeof(float);             // 65536
    const int EDGE_SMEM = (64 * SPAD + 8192) * (int)sizeof(float);// 67584
    const int TOPK_SMEM = NN * (int)sizeof(float);                // 40000
    cudaFuncSetAttribute(node_mma_kernel, cudaFuncAttributeMaxDynamicSharedMemorySize, GEMM_SMEM);
    cudaFuncSetAttribute(gram_mma_kernel, cudaFuncAttributeMaxDynamicSharedMemorySize, GEMM_SMEM);
    cudaFuncSetAttribute(edge_mma_kernel, cudaFuncAttributeMaxDynamicSharedMemorySize, EDGE_SMEM);
    cudaFuncSetAttribute(topk_kernel,     cudaFuncAttributeMaxDynamicSharedMemorySize, TOPK_SMEM);

    xfrag_kernel<<<dim3(8, NBLK), 256>>>(x);                      // 1
    norms_kernel<<<1250, 256>>>(x);                               // 2
    gram_mma_kernel<<<dim3(79, 79), 256, GEMM_SMEM>>>();          // 3
    topk_kernel<<<NN, 256, TOPK_SMEM>>>();                        // 4  <- profiled
    wfrag_kernel<<<dim3(8, 14), 256>>>(Wq, Wk, W1, W2);           // 5
    build_bias_kernel<<<7, 256>>>(bq, bk, b1, b2);                // 6
    node_mma_kernel<<<dim3(14, 79), 256, GEMM_SMEM>>>();          // 7
    edge_mma_kernel<<<dim3(2, 1250), 256, EDGE_SMEM>>>();         // 8
    combine_kernel<<<NN, 128>>>(out);                             // 9
}